// round 1
// baseline (speedup 1.0000x reference)
#include <cuda_runtime.h>
#include <cuda_bf16.h>
#include <cfloat>
#include <cstdint>

// Problem constants
#define BATCH 4
#define LSEQ 1024
#define NHEADS 32
#define NKV 8
#define HDIM 128
#define SAMPLE_Q 128
#define KEEP 512
#define SCALE_F 0.08838834764831844f   // 128^-0.5

#define QK_PAD 68

// ---------------- device scratch (no allocations allowed) ----------------
__device__ float2 g_ml[BATCH * NHEADS * SAMPLE_Q];       // per-row (m, l) for sample rows
__device__ float  g_part[BATCH * NHEADS * 2 * LSEQ];     // per (b,h,qs) importance partials
__device__ float  g_imp[BATCH * LSEQ];                   // reduced importance
__device__ int    g_keep[BATCH * KEEP];                  // sorted kept indices

// ---------------- cache passthrough ----------------
__global__ void copy_caches_kernel(const float4* __restrict__ kc, const float4* __restrict__ vc,
                                   float4* __restrict__ kco, float4* __restrict__ vco) {
    size_t i = (size_t)blockIdx.x * blockDim.x + threadIdx.x;   // 8192*256 = 2,097,152 exactly
    kco[i] = kc[i];
    vco[i] = vc[i];
}

// ---------------- main flash attention (fp32, register-tiled 64x64) ----------------
struct AttnSmem {
    float qs[HDIM][QK_PAD];   // [d][q] transposed, padded for float4 + conflict-free
    float ks[HDIM][QK_PAD];   // [d][k]
    float vs[64][HDIM];       // [k][d] natural
    float ps[64][QK_PAD];     // [k][q] transposed
};

__global__ void __launch_bounds__(128, 1)
attn_kernel(const float* __restrict__ q, const float* __restrict__ k,
            const float* __restrict__ v, float* __restrict__ o)
{
    extern __shared__ char smem_raw[];
    AttnSmem& sm = *reinterpret_cast<AttnSmem*>(smem_raw);

    const int qt = blockIdx.x;          // 16 q-tiles of 64
    const int h  = blockIdx.y;          // 32 heads
    const int b  = blockIdx.z;          // 4 batches
    const int kvh = h >> 2;
    const int tid = threadIdx.x;        // 128
    const int rg = tid >> 3;            // 16 row groups (4 q rows each)
    const int cg = tid & 7;             // 8 col groups
    const int rg4 = rg * 4, cg8 = cg * 8, cg16 = cg * 16;

    // load + pre-scale Q tile, transposed [d][q]
    const float* qbase = q + ((size_t)(b * LSEQ + qt * 64) * NHEADS + h) * HDIM;
    #pragma unroll 8
    for (int ql = 0; ql < 64; ++ql)
        sm.qs[tid][ql] = qbase[(size_t)ql * (NHEADS * HDIM) + tid] * SCALE_F;

    float acc[4][16];
    #pragma unroll
    for (int i = 0; i < 4; ++i)
        #pragma unroll
        for (int dd = 0; dd < 16; ++dd) acc[i][dd] = 0.f;
    float m_i[4] = {-FLT_MAX, -FLT_MAX, -FLT_MAX, -FLT_MAX};
    float l_i[4] = {0.f, 0.f, 0.f, 0.f};

    for (int kt = 0; kt <= qt; ++kt) {
        __syncthreads();   // previous PV reads / Q fill complete before refill
        const float* kb_ = k + ((size_t)(b * LSEQ + kt * 64) * NKV + kvh) * HDIM;
        const float* vb_ = v + ((size_t)(b * LSEQ + kt * 64) * NKV + kvh) * HDIM;
        #pragma unroll 8
        for (int kl = 0; kl < 64; ++kl)
            sm.ks[tid][kl] = kb_[(size_t)kl * (NKV * HDIM) + tid];
        {
            const float4* v4 = (const float4*)vb_;
            float4* vsh4 = (float4*)&sm.vs[0][0];
            #pragma unroll
            for (int it = 0; it < 16; ++it) {
                int idx = it * 128 + tid;                    // 0..2047
                vsh4[idx] = v4[(size_t)(idx >> 5) * (NKV * HDIM / 4) + (idx & 31)];
            }
        }
        __syncthreads();

        // S = Q^T K tile (4q x 8k per thread)
        float s[4][8];
        #pragma unroll
        for (int i = 0; i < 4; ++i)
            #pragma unroll
            for (int j = 0; j < 8; ++j) s[i][j] = 0.f;

        #pragma unroll 4
        for (int dd = 0; dd < HDIM; ++dd) {
            float4 af = *(const float4*)&sm.qs[dd][rg4];
            float4 b0 = *(const float4*)&sm.ks[dd][cg8];
            float4 b1 = *(const float4*)&sm.ks[dd][cg8 + 4];
            float a[4] = {af.x, af.y, af.z, af.w};
            float bb[8] = {b0.x, b0.y, b0.z, b0.w, b1.x, b1.y, b1.z, b1.w};
            #pragma unroll
            for (int i = 0; i < 4; ++i)
                #pragma unroll
                for (int j = 0; j < 8; ++j) s[i][j] += a[i] * bb[j];
        }

        if (kt == qt) {   // causal mask on diagonal tile
            #pragma unroll
            for (int i = 0; i < 4; ++i)
                #pragma unroll
                for (int j = 0; j < 8; ++j)
                    if (cg8 + j > rg4 + i) s[i][j] = -1e30f;
        }

        // online softmax per q row (reduction across the 8-lane cg group)
        #pragma unroll
        for (int i = 0; i < 4; ++i) {
            float tmax = s[i][0];
            #pragma unroll
            for (int j = 1; j < 8; ++j) tmax = fmaxf(tmax, s[i][j]);
            tmax = fmaxf(tmax, __shfl_xor_sync(0xffffffffu, tmax, 1, 8));
            tmax = fmaxf(tmax, __shfl_xor_sync(0xffffffffu, tmax, 2, 8));
            tmax = fmaxf(tmax, __shfl_xor_sync(0xffffffffu, tmax, 4, 8));
            float mnew = fmaxf(m_i[i], tmax);
            float corr = __expf(m_i[i] - mnew);
            float rsum = 0.f;
            #pragma unroll
            for (int j = 0; j < 8; ++j) {
                float p = __expf(s[i][j] - mnew);
                rsum += p;
                sm.ps[cg8 + j][rg4 + i] = p;
            }
            rsum += __shfl_xor_sync(0xffffffffu, rsum, 1, 8);
            rsum += __shfl_xor_sync(0xffffffffu, rsum, 2, 8);
            rsum += __shfl_xor_sync(0xffffffffu, rsum, 4, 8);
            l_i[i] = l_i[i] * corr + rsum;
            m_i[i] = mnew;
            #pragma unroll
            for (int dd = 0; dd < 16; ++dd) acc[i][dd] *= corr;
        }
        __syncthreads();

        // O += P V (4q x 16d per thread)
        #pragma unroll 2
        for (int kk = 0; kk < 64; ++kk) {
            float4 pf = *(const float4*)&sm.ps[kk][rg4];
            float pv[4] = {pf.x, pf.y, pf.z, pf.w};
            const float* vrow = &sm.vs[kk][cg16];
            float4 v0 = *(const float4*)(vrow);
            float4 v1 = *(const float4*)(vrow + 4);
            float4 v2 = *(const float4*)(vrow + 8);
            float4 v3 = *(const float4*)(vrow + 12);
            float vv[16] = {v0.x, v0.y, v0.z, v0.w, v1.x, v1.y, v1.z, v1.w,
                            v2.x, v2.y, v2.z, v2.w, v3.x, v3.y, v3.z, v3.w};
            #pragma unroll
            for (int i = 0; i < 4; ++i)
                #pragma unroll
                for (int dd = 0; dd < 16; ++dd) acc[i][dd] += pv[i] * vv[dd];
        }
    }

    // epilogue: normalize + store; also stash (m,l) for SnapKV sample rows
    #pragma unroll
    for (int i = 0; i < 4; ++i) {
        float inv = 1.f / l_i[i];
        int row = qt * 64 + rg4 + i;
        float* orow = o + ((size_t)(b * LSEQ + row) * NHEADS + h) * HDIM + cg16;
        *(float4*)(orow)      = make_float4(acc[i][0] * inv, acc[i][1] * inv, acc[i][2] * inv, acc[i][3] * inv);
        *(float4*)(orow + 4)  = make_float4(acc[i][4] * inv, acc[i][5] * inv, acc[i][6] * inv, acc[i][7] * inv);
        *(float4*)(orow + 8)  = make_float4(acc[i][8] * inv, acc[i][9] * inv, acc[i][10] * inv, acc[i][11] * inv);
        *(float4*)(orow + 12) = make_float4(acc[i][12] * inv, acc[i][13] * inv, acc[i][14] * inv, acc[i][15] * inv);
        if (qt >= 14 && cg == 0)
            g_ml[(b * NHEADS + h) * SAMPLE_Q + (qt - 14) * 64 + rg4 + i] = make_float2(m_i[i], l_i[i]);
    }
}

// ---------------- SnapKV sample scores: recompute S, normalize with stored (m,l) ----------------
struct SampSmem {
    float qs[HDIM][QK_PAD];
    float ks[HDIM][QK_PAD];
    float colpart[16][64];
};

__global__ void __launch_bounds__(128)
sample_kernel(const float* __restrict__ q, const float* __restrict__ k)
{
    extern __shared__ char smem_raw[];
    SampSmem& sm = *reinterpret_cast<SampSmem*>(smem_raw);

    const int kt = blockIdx.x;          // 16 k-tiles
    const int qs = blockIdx.y;          // 2 q-tiles of the sample window
    const int bh = blockIdx.z;          // 128 (b,h)
    const int b = bh >> 5, h = bh & 31, kvh = h >> 2;
    const int tid = threadIdx.x;
    const int rg = tid >> 3, cg = tid & 7;
    const int rg4 = rg * 4, cg8 = cg * 8;

    const float* qbase = q + ((size_t)(b * LSEQ + (LSEQ - SAMPLE_Q) + qs * 64) * NHEADS + h) * HDIM;
    #pragma unroll 8
    for (int ql = 0; ql < 64; ++ql)
        sm.qs[tid][ql] = qbase[(size_t)ql * (NHEADS * HDIM) + tid] * SCALE_F;
    const float* kb_ = k + ((size_t)(b * LSEQ + kt * 64) * NKV + kvh) * HDIM;
    #pragma unroll 8
    for (int kl = 0; kl < 64; ++kl)
        sm.ks[tid][kl] = kb_[(size_t)kl * (NKV * HDIM) + tid];
    __syncthreads();

    float s[4][8];
    #pragma unroll
    for (int i = 0; i < 4; ++i)
        #pragma unroll
        for (int j = 0; j < 8; ++j) s[i][j] = 0.f;

    #pragma unroll 4
    for (int dd = 0; dd < HDIM; ++dd) {
        float4 af = *(const float4*)&sm.qs[dd][rg4];
        float4 b0 = *(const float4*)&sm.ks[dd][cg8];
        float4 b1 = *(const float4*)&sm.ks[dd][cg8 + 4];
        float a[4] = {af.x, af.y, af.z, af.w};
        float bb[8] = {b0.x, b0.y, b0.z, b0.w, b1.x, b1.y, b1.z, b1.w};
        #pragma unroll
        for (int i = 0; i < 4; ++i)
            #pragma unroll
            for (int j = 0; j < 8; ++j) s[i][j] += a[i] * bb[j];
    }

    float psum[8] = {0.f, 0.f, 0.f, 0.f, 0.f, 0.f, 0.f, 0.f};
    #pragma unroll
    for (int i = 0; i < 4; ++i) {
        int qrow = qs * 64 + rg4 + i;                       // 0..127 in sample window
        float2 mlv = g_ml[bh * SAMPLE_Q + qrow];
        float m = mlv.x, invl = 1.f / mlv.y;
        int q_abs = (LSEQ - SAMPLE_Q) + qrow;
        #pragma unroll
        for (int j = 0; j < 8; ++j) {
            int k_abs = kt * 64 + cg8 + j;
            if (k_abs <= q_abs) psum[j] += __expf(s[i][j] - m) * invl;
        }
    }
    #pragma unroll
    for (int j = 0; j < 8; ++j) sm.colpart[rg][cg8 + j] = psum[j];
    __syncthreads();

    if (tid < 64) {
        float sum = 0.f;
        #pragma unroll
        for (int r2 = 0; r2 < 16; ++r2) sum += sm.colpart[r2][tid];
        g_part[((size_t)bh * 2 + qs) * LSEQ + kt * 64 + tid] = sum;
    }
}

// ---------------- deterministic reduce over (h, qs) ----------------
__global__ void reduce_kernel() {
    int idx = blockIdx.x * 256 + threadIdx.x;   // 4096
    int b = idx >> 10, kk = idx & 1023;
    float s = 0.f;
    #pragma unroll
    for (int t = 0; t < NHEADS * 2; ++t)
        s += g_part[((size_t)(b * NHEADS * 2 + t)) * LSEQ + kk];
    g_imp[idx] = s;
}

// ---------------- exact top-512 + ascending sort (stable tie-break = lower index) ----------------
__global__ void topk_kernel() {
    const int b = blockIdx.x;
    const int tid = threadIdx.x;                // 1024
    __shared__ float vals[LSEQ];
    __shared__ unsigned flags[32];
    vals[tid] = g_imp[b * LSEQ + tid];
    __syncthreads();
    float v = vals[tid];
    int cnt = 0;
    for (int j = 0; j < LSEQ; ++j) {
        float w = vals[j];
        cnt += (w > v) || (w == v && j < tid);
    }
    bool kept = (cnt < KEEP);
    unsigned bal = __ballot_sync(0xffffffffu, kept);
    if ((tid & 31) == 0) flags[tid >> 5] = bal;
    __syncthreads();
    if (kept) {
        int w = tid >> 5;
        int pos = 0;
        for (int t = 0; t < w; ++t) pos += __popc(flags[t]);
        pos += __popc(flags[w] & ((1u << (tid & 31)) - 1u));
        g_keep[b * KEEP + pos] = tid;
    }
}

// ---------------- gather kept tokens, scatter to cache slots ----------------
__global__ void scatter_kernel(const float* __restrict__ k, const float* __restrict__ v,
                               const int* __restrict__ slot_map,
                               float* __restrict__ kco, float* __restrict__ vco) {
    int r = blockIdx.x;                         // 2048 rows
    int b = r >> 9, j = r & 511;
    int src = b * LSEQ + g_keep[b * KEEP + j];
    int dst = slot_map[b * LSEQ + j];
    const float4* ks = (const float4*)(k + (size_t)src * (NKV * HDIM));
    const float4* vs = (const float4*)(v + (size_t)src * (NKV * HDIM));
    float4* kd = (float4*)(kco + (size_t)dst * (NKV * HDIM));
    float4* vd = (float4*)(vco + (size_t)dst * (NKV * HDIM));
    kd[threadIdx.x] = ks[threadIdx.x];          // 256 threads * 16B = 1024 floats
    vd[threadIdx.x] = vs[threadIdx.x];
}

// ---------------- launch ----------------
extern "C" void kernel_launch(void* const* d_in, const int* in_sizes, int n_in,
                              void* d_out, int out_size) {
    const float* q  = (const float*)d_in[0];
    const float* k  = (const float*)d_in[1];
    const float* v  = (const float*)d_in[2];
    const float* kc = (const float*)d_in[3];
    const float* vc = (const float*)d_in[4];
    const int* slot = (const int*)d_in[5];

    float* o   = (float*)d_out;
    float* kco = o + (size_t)BATCH * LSEQ * NHEADS * HDIM;       // 16,777,216
    float* vco = kco + (size_t)8192 * (NKV * HDIM);              // +8,388,608

    cudaFuncSetAttribute(attn_kernel, cudaFuncAttributeMaxDynamicSharedMemorySize, (int)sizeof(AttnSmem));
    cudaFuncSetAttribute(sample_kernel, cudaFuncAttributeMaxDynamicSharedMemorySize, (int)sizeof(SampSmem));

    copy_caches_kernel<<<8192, 256>>>((const float4*)kc, (const float4*)vc,
                                      (float4*)kco, (float4*)vco);
    attn_kernel<<<dim3(16, NHEADS, BATCH), 128, sizeof(AttnSmem)>>>(q, k, v, o);
    sample_kernel<<<dim3(16, 2, BATCH * NHEADS), 128, sizeof(SampSmem)>>>(q, k);
    reduce_kernel<<<16, 256>>>();
    topk_kernel<<<BATCH, 1024>>>();
    scatter_kernel<<<2048, 256>>>(k, v, slot, kco, vco);
}

// round 2
// speedup vs baseline: 3.5854x; 3.5854x over previous
#include <cuda_runtime.h>
#include <cuda_bf16.h>
#include <cfloat>
#include <cstdint>

#define BATCH 4
#define LSEQ 1024
#define NHEADS 32
#define NKV 8
#define HDIM 128
#define SAMPLE_Q 128
#define KEEP 512
#define SCALE_F 0.08838834764831844f   // 128^-0.5

#define QSTR 132   // Q/K row-major stride (uint32) -> (4g+t) bank map, conflict-free
#define VSTR 136   // V stride -> (8t+g) bank map, conflict-free
#define PSTR 68    // P stride -> (4g+t) bank map, conflict-free

// ---------------- device scratch ----------------
__device__ float2 g_ml[BATCH * NHEADS * SAMPLE_Q];
__device__ float  g_part[BATCH * NHEADS * LSEQ];
__device__ float  g_imp[BATCH * LSEQ];
__device__ int    g_keep[BATCH * KEEP];

__device__ __forceinline__ uint32_t f2tf(float x) {
    uint32_t r; asm("cvt.rna.tf32.f32 %0, %1;" : "=r"(r) : "f"(x)); return r;
}

__device__ __forceinline__ void mma8(float* c, const uint32_t* a, const uint32_t* b) {
    asm volatile("mma.sync.aligned.m16n8k8.row.col.f32.tf32.tf32.f32 "
                 "{%0,%1,%2,%3}, {%4,%5,%6,%7}, {%8,%9}, {%0,%1,%2,%3};"
                 : "+f"(c[0]), "+f"(c[1]), "+f"(c[2]), "+f"(c[3])
                 : "r"(a[0]), "r"(a[1]), "r"(a[2]), "r"(a[3]), "r"(b[0]), "r"(b[1]));
}

// ---------------- cache passthrough ----------------
__global__ void copy_caches_kernel(const float4* __restrict__ kc, const float4* __restrict__ vc,
                                   float4* __restrict__ kco, float4* __restrict__ vco) {
    size_t i = (size_t)blockIdx.x * blockDim.x + threadIdx.x;
    kco[i] = kc[i];
    vco[i] = vc[i];
}

// ---------------- main flash attention: tf32 mma.sync, Bq=128 x Bk=64 ----------------
struct AttnSmem {
    uint32_t qs[128 * QSTR];   // Q tile, tf32, row-major [qrow][d]
    uint32_t ks[64 * QSTR];    // K tile, tf32, row-major [kcol][d]
    uint32_t vs[64 * VSTR];    // V tile, tf32, row-major [krow][d]
    uint32_t ps[128 * PSTR];   // P tile, tf32, row-major [qrow][kcol]
};

__global__ void __launch_bounds__(256, 1)
attn_kernel(const float* __restrict__ q, const float* __restrict__ k,
            const float* __restrict__ v, float* __restrict__ o)
{
    extern __shared__ char raw[];
    AttnSmem& sm = *reinterpret_cast<AttnSmem*>(raw);

    const int qt = blockIdx.x;          // 8 q-tiles of 128
    const int h  = blockIdx.y;
    const int b  = blockIdx.z;
    const int kvh = h >> 2;
    const int tid = threadIdx.x;
    const int w = tid >> 5, lane = tid & 31;
    const int g = lane >> 2, t = lane & 3;
    const int qb = w * 16;              // warp's 16 q-rows

    // Q tile -> smem as tf32 (warp w: rows qb..qb+15, coalesced float4)
    {
        const float* qg = q + ((size_t)(b * LSEQ + qt * 128 + qb) * NHEADS + h) * HDIM;
        #pragma unroll 4
        for (int r = 0; r < 16; ++r) {
            float4 f = *(const float4*)(qg + (size_t)r * NHEADS * HDIM + lane * 4);
            uint32_t* d = &sm.qs[(qb + r) * QSTR + lane * 4];
            d[0] = f2tf(f.x); d[1] = f2tf(f.y); d[2] = f2tf(f.z); d[3] = f2tf(f.w);
        }
    }

    float oacc[16][4];
    #pragma unroll
    for (int nf = 0; nf < 16; ++nf)
        #pragma unroll
        for (int j = 0; j < 4; ++j) oacc[nf][j] = 0.f;
    float m0 = -FLT_MAX, m1 = -FLT_MAX, l0 = 0.f, l1 = 0.f;

    const int nkt = 2 * qt + 2;
    for (int kt = 0; kt < nkt; ++kt) {
        __syncthreads();   // prior PV reads done; Q tile visible on first iter
        // K,V tiles -> smem as tf32 (warp w: rows w*8..w*8+7)
        {
            const float* kg = k + ((size_t)(b * LSEQ + kt * 64 + w * 8) * NKV + kvh) * HDIM;
            const float* vg = v + ((size_t)(b * LSEQ + kt * 64 + w * 8) * NKV + kvh) * HDIM;
            #pragma unroll
            for (int r = 0; r < 8; ++r) {
                float4 f = *(const float4*)(kg + (size_t)r * NKV * HDIM + lane * 4);
                uint32_t* d = &sm.ks[(w * 8 + r) * QSTR + lane * 4];
                d[0] = f2tf(f.x); d[1] = f2tf(f.y); d[2] = f2tf(f.z); d[3] = f2tf(f.w);
                float4 fv = *(const float4*)(vg + (size_t)r * NKV * HDIM + lane * 4);
                uint32_t* dv = &sm.vs[(w * 8 + r) * VSTR + lane * 4];
                dv[0] = f2tf(fv.x); dv[1] = f2tf(fv.y); dv[2] = f2tf(fv.z); dv[3] = f2tf(fv.w);
            }
        }
        __syncthreads();

        // ---- S = Q K^T ----
        float s[8][4];
        #pragma unroll
        for (int nf = 0; nf < 8; ++nf)
            #pragma unroll
            for (int j = 0; j < 4; ++j) s[nf][j] = 0.f;

        #pragma unroll
        for (int ks = 0; ks < 16; ++ks) {
            uint32_t a[4];
            const uint32_t* q0 = &sm.qs[(qb + g) * QSTR + ks * 8 + t];
            const uint32_t* q1 = &sm.qs[(qb + g + 8) * QSTR + ks * 8 + t];
            a[0] = q0[0]; a[1] = q1[0]; a[2] = q0[4]; a[3] = q1[4];
            #pragma unroll
            for (int nf = 0; nf < 8; ++nf) {
                uint32_t bf[2];
                const uint32_t* kr = &sm.ks[(nf * 8 + g) * QSTR + ks * 8 + t];
                bf[0] = kr[0]; bf[1] = kr[4];
                mma8(s[nf], a, bf);
            }
        }

        #pragma unroll
        for (int nf = 0; nf < 8; ++nf)
            #pragma unroll
            for (int j = 0; j < 4; ++j) s[nf][j] *= SCALE_F;

        if (kt >= 2 * qt) {  // causal mask on diagonal tiles
            int r0 = qt * 128 + qb + g, r1 = r0 + 8;
            #pragma unroll
            for (int nf = 0; nf < 8; ++nf) {
                int c0 = kt * 64 + nf * 8 + 2 * t, c1 = c0 + 1;
                if (c0 > r0) s[nf][0] = -1e30f;
                if (c1 > r0) s[nf][1] = -1e30f;
                if (c0 > r1) s[nf][2] = -1e30f;
                if (c1 > r1) s[nf][3] = -1e30f;
            }
        }

        // ---- online softmax (rows g and g+8 of this warp) ----
        float mx0 = -FLT_MAX, mx1 = -FLT_MAX;
        #pragma unroll
        for (int nf = 0; nf < 8; ++nf) {
            mx0 = fmaxf(mx0, fmaxf(s[nf][0], s[nf][1]));
            mx1 = fmaxf(mx1, fmaxf(s[nf][2], s[nf][3]));
        }
        mx0 = fmaxf(mx0, __shfl_xor_sync(0xffffffffu, mx0, 1));
        mx0 = fmaxf(mx0, __shfl_xor_sync(0xffffffffu, mx0, 2));
        mx1 = fmaxf(mx1, __shfl_xor_sync(0xffffffffu, mx1, 1));
        mx1 = fmaxf(mx1, __shfl_xor_sync(0xffffffffu, mx1, 2));
        float mn0 = fmaxf(m0, mx0), mn1 = fmaxf(m1, mx1);
        float cf0 = __expf(m0 - mn0), cf1 = __expf(m1 - mn1);
        float sum0 = 0.f, sum1 = 0.f;
        #pragma unroll
        for (int nf = 0; nf < 8; ++nf) {
            float p00 = __expf(s[nf][0] - mn0);
            float p01 = __expf(s[nf][1] - mn0);
            float p10 = __expf(s[nf][2] - mn1);
            float p11 = __expf(s[nf][3] - mn1);
            sum0 += p00 + p01; sum1 += p10 + p11;
            *(uint2*)&sm.ps[(qb + g) * PSTR + nf * 8 + 2 * t]     = make_uint2(f2tf(p00), f2tf(p01));
            *(uint2*)&sm.ps[(qb + g + 8) * PSTR + nf * 8 + 2 * t] = make_uint2(f2tf(p10), f2tf(p11));
        }
        sum0 += __shfl_xor_sync(0xffffffffu, sum0, 1);
        sum0 += __shfl_xor_sync(0xffffffffu, sum0, 2);
        sum1 += __shfl_xor_sync(0xffffffffu, sum1, 1);
        sum1 += __shfl_xor_sync(0xffffffffu, sum1, 2);
        l0 = l0 * cf0 + sum0; l1 = l1 * cf1 + sum1;
        m0 = mn0; m1 = mn1;
        #pragma unroll
        for (int nf = 0; nf < 16; ++nf) {
            oacc[nf][0] *= cf0; oacc[nf][1] *= cf0;
            oacc[nf][2] *= cf1; oacc[nf][3] *= cf1;
        }
        __syncwarp();   // P stores visible to quad-mates before A-frag loads

        // ---- O += P V ---- (ps rows of this warp only -> no block sync needed)
        #pragma unroll
        for (int ks2 = 0; ks2 < 8; ++ks2) {
            uint32_t a[4];
            const uint32_t* p0 = &sm.ps[(qb + g) * PSTR + ks2 * 8 + t];
            const uint32_t* p1 = &sm.ps[(qb + g + 8) * PSTR + ks2 * 8 + t];
            a[0] = p0[0]; a[1] = p1[0]; a[2] = p0[4]; a[3] = p1[4];
            #pragma unroll
            for (int nf = 0; nf < 16; ++nf) {
                uint32_t bf[2];
                bf[0] = sm.vs[(ks2 * 8 + t) * VSTR + nf * 8 + g];
                bf[1] = sm.vs[(ks2 * 8 + t + 4) * VSTR + nf * 8 + g];
                mma8(oacc[nf], a, bf);
            }
        }
    }

    // ---- epilogue ----
    float inv0 = 1.f / l0, inv1 = 1.f / l1;
    int r0 = qt * 128 + qb + g;
    float* o0 = o + ((size_t)(b * LSEQ + r0) * NHEADS + h) * HDIM;
    float* o1 = o0 + (size_t)8 * NHEADS * HDIM;
    #pragma unroll
    for (int nf = 0; nf < 16; ++nf) {
        *(float2*)&o0[nf * 8 + 2 * t] = make_float2(oacc[nf][0] * inv0, oacc[nf][1] * inv0);
        *(float2*)&o1[nf * 8 + 2 * t] = make_float2(oacc[nf][2] * inv1, oacc[nf][3] * inv1);
    }
    if (qt == 7 && t == 0) {
        g_ml[(b * NHEADS + h) * SAMPLE_Q + qb + g]     = make_float2(m0, l0);
        g_ml[(b * NHEADS + h) * SAMPLE_Q + qb + g + 8] = make_float2(m1, l1);
    }
}

// ---------------- SnapKV sample scores (tf32 mma) ----------------
struct SampSmem {
    uint32_t qs[128 * QSTR];
    uint32_t ks[64 * QSTR];
    float colpart[8][64];
};

__global__ void __launch_bounds__(256)
sample_kernel(const float* __restrict__ q, const float* __restrict__ k)
{
    extern __shared__ char raw[];
    SampSmem& sm = *reinterpret_cast<SampSmem*>(raw);

    const int kt = blockIdx.x;          // 16 k-tiles of 64
    const int bh = blockIdx.y;          // 128
    const int b = bh >> 5, h = bh & 31, kvh = h >> 2;
    const int tid = threadIdx.x;
    const int w = tid >> 5, lane = tid & 31;
    const int g = lane >> 2, t = lane & 3;
    const int qb = w * 16;

    {
        const float* qg = q + ((size_t)(b * LSEQ + (LSEQ - SAMPLE_Q) + qb) * NHEADS + h) * HDIM;
        #pragma unroll 4
        for (int r = 0; r < 16; ++r) {
            float4 f = *(const float4*)(qg + (size_t)r * NHEADS * HDIM + lane * 4);
            uint32_t* d = &sm.qs[(qb + r) * QSTR + lane * 4];
            d[0] = f2tf(f.x); d[1] = f2tf(f.y); d[2] = f2tf(f.z); d[3] = f2tf(f.w);
        }
        const float* kg = k + ((size_t)(b * LSEQ + kt * 64 + w * 8) * NKV + kvh) * HDIM;
        #pragma unroll
        for (int r = 0; r < 8; ++r) {
            float4 f = *(const float4*)(kg + (size_t)r * NKV * HDIM + lane * 4);
            uint32_t* d = &sm.ks[(w * 8 + r) * QSTR + lane * 4];
            d[0] = f2tf(f.x); d[1] = f2tf(f.y); d[2] = f2tf(f.z); d[3] = f2tf(f.w);
        }
    }
    __syncthreads();

    float s[8][4];
    #pragma unroll
    for (int nf = 0; nf < 8; ++nf)
        #pragma unroll
        for (int j = 0; j < 4; ++j) s[nf][j] = 0.f;

    #pragma unroll
    for (int ks = 0; ks < 16; ++ks) {
        uint32_t a[4];
        const uint32_t* q0 = &sm.qs[(qb + g) * QSTR + ks * 8 + t];
        const uint32_t* q1 = &sm.qs[(qb + g + 8) * QSTR + ks * 8 + t];
        a[0] = q0[0]; a[1] = q1[0]; a[2] = q0[4]; a[3] = q1[4];
        #pragma unroll
        for (int nf = 0; nf < 8; ++nf) {
            uint32_t bf[2];
            const uint32_t* kr = &sm.ks[(nf * 8 + g) * QSTR + ks * 8 + t];
            bf[0] = kr[0]; bf[1] = kr[4];
            mma8(s[nf], a, bf);
        }
    }

    float2 ml0 = g_ml[bh * SAMPLE_Q + qb + g];
    float2 ml1 = g_ml[bh * SAMPLE_Q + qb + g + 8];
    float il0 = 1.f / ml0.y, il1 = 1.f / ml1.y;
    int r0 = (LSEQ - SAMPLE_Q) + qb + g, r1 = r0 + 8;

    float cp[16];
    #pragma unroll
    for (int j = 0; j < 16; ++j) cp[j] = 0.f;
    #pragma unroll
    for (int nf = 0; nf < 8; ++nf) {
        int c0 = kt * 64 + nf * 8 + 2 * t, c1 = c0 + 1;
        float p00 = (c0 <= r0) ? __expf(s[nf][0] * SCALE_F - ml0.x) * il0 : 0.f;
        float p01 = (c1 <= r0) ? __expf(s[nf][1] * SCALE_F - ml0.x) * il0 : 0.f;
        float p10 = (c0 <= r1) ? __expf(s[nf][2] * SCALE_F - ml1.x) * il1 : 0.f;
        float p11 = (c1 <= r1) ? __expf(s[nf][3] * SCALE_F - ml1.x) * il1 : 0.f;
        cp[nf * 2]     += p00 + p10;
        cp[nf * 2 + 1] += p01 + p11;
    }
    // reduce over g (lanes l = 4g+t share t)
    #pragma unroll
    for (int d = 4; d < 32; d <<= 1)
        #pragma unroll
        for (int j = 0; j < 16; ++j)
            cp[j] += __shfl_xor_sync(0xffffffffu, cp[j], d);
    if (g == 0) {
        #pragma unroll
        for (int nf = 0; nf < 8; ++nf) {
            sm.colpart[w][nf * 8 + 2 * t]     = cp[nf * 2];
            sm.colpart[w][nf * 8 + 2 * t + 1] = cp[nf * 2 + 1];
        }
    }
    __syncthreads();
    if (tid < 64) {
        float ssum = 0.f;
        #pragma unroll
        for (int ww = 0; ww < 8; ++ww) ssum += sm.colpart[ww][tid];
        g_part[(size_t)bh * LSEQ + kt * 64 + tid] = ssum;
    }
}

// ---------------- deterministic reduce over heads ----------------
__global__ void reduce_kernel() {
    int idx = blockIdx.x * 256 + threadIdx.x;   // 4096
    int b = idx >> 10, kk = idx & 1023;
    float s = 0.f;
    #pragma unroll
    for (int h = 0; h < NHEADS; ++h)
        s += g_part[(size_t)(b * NHEADS + h) * LSEQ + kk];
    g_imp[idx] = s;
}

// ---------------- exact top-512 + ascending sort ----------------
__global__ void topk_kernel() {
    const int b = blockIdx.x;
    const int tid = threadIdx.x;                // 1024
    __shared__ float vals[LSEQ];
    __shared__ unsigned flags[32];
    vals[tid] = g_imp[b * LSEQ + tid];
    __syncthreads();
    float v = vals[tid];
    int cnt = 0;
    for (int j = 0; j < LSEQ; ++j) {
        float wv = vals[j];
        cnt += (wv > v) || (wv == v && j < tid);
    }
    bool kept = (cnt < KEEP);
    unsigned bal = __ballot_sync(0xffffffffu, kept);
    if ((tid & 31) == 0) flags[tid >> 5] = bal;
    __syncthreads();
    if (kept) {
        int wq = tid >> 5;
        int pos = 0;
        for (int tq = 0; tq < wq; ++tq) pos += __popc(flags[tq]);
        pos += __popc(flags[wq] & ((1u << (tid & 31)) - 1u));
        g_keep[b * KEEP + pos] = tid;
    }
}

// ---------------- gather kept tokens, scatter to cache slots ----------------
__global__ void scatter_kernel(const float* __restrict__ k, const float* __restrict__ v,
                               const int* __restrict__ slot_map,
                               float* __restrict__ kco, float* __restrict__ vco) {
    int r = blockIdx.x;                         // 2048 rows
    int b = r >> 9, j = r & 511;
    int src = b * LSEQ + g_keep[b * KEEP + j];
    int dst = slot_map[b * LSEQ + j];
    const float4* ks = (const float4*)(k + (size_t)src * (NKV * HDIM));
    const float4* vs = (const float4*)(v + (size_t)src * (NKV * HDIM));
    float4* kd = (float4*)(kco + (size_t)dst * (NKV * HDIM));
    float4* vd = (float4*)(vco + (size_t)dst * (NKV * HDIM));
    kd[threadIdx.x] = ks[threadIdx.x];
    vd[threadIdx.x] = vs[threadIdx.x];
}

// ---------------- launch ----------------
extern "C" void kernel_launch(void* const* d_in, const int* in_sizes, int n_in,
                              void* d_out, int out_size) {
    const float* q  = (const float*)d_in[0];
    const float* k  = (const float*)d_in[1];
    const float* v  = (const float*)d_in[2];
    const float* kc = (const float*)d_in[3];
    const float* vc = (const float*)d_in[4];
    const int* slot = (const int*)d_in[5];

    float* o   = (float*)d_out;
    float* kco = o + (size_t)BATCH * LSEQ * NHEADS * HDIM;
    float* vco = kco + (size_t)8192 * (NKV * HDIM);

    cudaFuncSetAttribute(attn_kernel, cudaFuncAttributeMaxDynamicSharedMemorySize, (int)sizeof(AttnSmem));
    cudaFuncSetAttribute(sample_kernel, cudaFuncAttributeMaxDynamicSharedMemorySize, (int)sizeof(SampSmem));

    copy_caches_kernel<<<8192, 256>>>((const float4*)kc, (const float4*)vc,
                                      (float4*)kco, (float4*)vco);
    attn_kernel<<<dim3(8, NHEADS, BATCH), 256, sizeof(AttnSmem)>>>(q, k, v, o);
    sample_kernel<<<dim3(16, BATCH * NHEADS), 256, sizeof(SampSmem)>>>(q, k);
    reduce_kernel<<<16, 256>>>();
    topk_kernel<<<BATCH, 1024>>>();
    scatter_kernel<<<2048, 256>>>(k, v, slot, kco, vco);
}

// round 3
// speedup vs baseline: 5.2895x; 1.4753x over previous
#include <cuda_runtime.h>
#include <cuda_bf16.h>
#include <cfloat>
#include <cstdint>

#define BATCH 4
#define LSEQ 1024
#define NHEADS 32
#define NKV 8
#define HDIM 128
#define SAMPLE_Q 128
#define KEEP 512
#define SCALE_F 0.08838834764831844f   // 128^-0.5

#define QSTR 132   // Q/K row-major stride (uint32) -> (4g+t) bank map, conflict-free
#define VSTR 136   // V stride -> (8t+g) bank map, conflict-free
#define PSTR 68    // P stride -> (4g+t) bank map, conflict-free

// ---------------- device scratch ----------------
__device__ float2 g_ml[BATCH * NHEADS * SAMPLE_Q];
__device__ float  g_part[BATCH * NHEADS * LSEQ];
__device__ float  g_imp[BATCH * LSEQ];
__device__ int    g_keep[BATCH * KEEP];

__device__ __forceinline__ uint32_t f2tf(float x) {
    uint32_t r; asm("cvt.rna.tf32.f32 %0, %1;" : "=r"(r) : "f"(x)); return r;
}

__device__ __forceinline__ void mma8(float* c, const uint32_t* a, const uint32_t* b) {
    asm volatile("mma.sync.aligned.m16n8k8.row.col.f32.tf32.tf32.f32 "
                 "{%0,%1,%2,%3}, {%4,%5,%6,%7}, {%8,%9}, {%0,%1,%2,%3};"
                 : "+f"(c[0]), "+f"(c[1]), "+f"(c[2]), "+f"(c[3])
                 : "r"(a[0]), "r"(a[1]), "r"(a[2]), "r"(a[3]), "r"(b[0]), "r"(b[1]));
}

// ---------------- cache passthrough ----------------
__global__ void copy_caches_kernel(const float4* __restrict__ kc, const float4* __restrict__ vc,
                                   float4* __restrict__ kco, float4* __restrict__ vco) {
    size_t i = (size_t)blockIdx.x * blockDim.x + threadIdx.x;
    kco[i] = kc[i];
    vco[i] = vc[i];
}

// ---------------- main flash attention: tf32 mma.sync, Bq=128 x Bk=64 ----------------
struct AttnSmem {
    uint32_t qs[128 * QSTR];   // Q tile, tf32, row-major [qrow][d]
    uint32_t ks[64 * QSTR];    // K tile, tf32, row-major [kcol][d]
    uint32_t vs[64 * VSTR];    // V tile, tf32, row-major [krow][d]
    uint32_t ps[128 * PSTR];   // P tile, tf32, row-major [qrow][kcol]
};

__global__ void __launch_bounds__(256, 1)
attn_kernel(const float* __restrict__ q, const float* __restrict__ k,
            const float* __restrict__ v, float* __restrict__ o)
{
    extern __shared__ char raw[];
    AttnSmem& sm = *reinterpret_cast<AttnSmem*>(raw);

    const int qt = blockIdx.x;          // 8 q-tiles of 128
    const int h  = blockIdx.y;
    const int b  = blockIdx.z;
    const int kvh = h >> 2;
    const int tid = threadIdx.x;
    const int w = tid >> 5, lane = tid & 31;
    const int g = lane >> 2, t = lane & 3;
    const int qb = w * 16;              // warp's 16 q-rows

    // Q tile -> smem as tf32 (warp w: rows qb..qb+15, coalesced float4)
    {
        const float* qg = q + ((size_t)(b * LSEQ + qt * 128 + qb) * NHEADS + h) * HDIM;
        #pragma unroll 4
        for (int r = 0; r < 16; ++r) {
            float4 f = *(const float4*)(qg + (size_t)r * NHEADS * HDIM + lane * 4);
            uint32_t* d = &sm.qs[(qb + r) * QSTR + lane * 4];
            d[0] = f2tf(f.x); d[1] = f2tf(f.y); d[2] = f2tf(f.z); d[3] = f2tf(f.w);
        }
    }

    float oacc[16][4];
    #pragma unroll
    for (int nf = 0; nf < 16; ++nf)
        #pragma unroll
        for (int j = 0; j < 4; ++j) oacc[nf][j] = 0.f;
    float m0 = -FLT_MAX, m1 = -FLT_MAX, l0 = 0.f, l1 = 0.f;

    const int nkt = 2 * qt + 2;
    for (int kt = 0; kt < nkt; ++kt) {
        __syncthreads();   // prior PV reads done; Q tile visible on first iter
        // K,V tiles -> smem as tf32 (warp w: rows w*8..w*8+7)
        {
            const float* kg = k + ((size_t)(b * LSEQ + kt * 64 + w * 8) * NKV + kvh) * HDIM;
            const float* vg = v + ((size_t)(b * LSEQ + kt * 64 + w * 8) * NKV + kvh) * HDIM;
            #pragma unroll
            for (int r = 0; r < 8; ++r) {
                float4 f = *(const float4*)(kg + (size_t)r * NKV * HDIM + lane * 4);
                uint32_t* d = &sm.ks[(w * 8 + r) * QSTR + lane * 4];
                d[0] = f2tf(f.x); d[1] = f2tf(f.y); d[2] = f2tf(f.z); d[3] = f2tf(f.w);
                float4 fv = *(const float4*)(vg + (size_t)r * NKV * HDIM + lane * 4);
                uint32_t* dv = &sm.vs[(w * 8 + r) * VSTR + lane * 4];
                dv[0] = f2tf(fv.x); dv[1] = f2tf(fv.y); dv[2] = f2tf(fv.z); dv[3] = f2tf(fv.w);
            }
        }
        __syncthreads();

        // ---- S = Q K^T ----
        float s[8][4];
        #pragma unroll
        for (int nf = 0; nf < 8; ++nf)
            #pragma unroll
            for (int j = 0; j < 4; ++j) s[nf][j] = 0.f;

        #pragma unroll
        for (int ks = 0; ks < 16; ++ks) {
            uint32_t a[4];
            const uint32_t* q0 = &sm.qs[(qb + g) * QSTR + ks * 8 + t];
            const uint32_t* q1 = &sm.qs[(qb + g + 8) * QSTR + ks * 8 + t];
            a[0] = q0[0]; a[1] = q1[0]; a[2] = q0[4]; a[3] = q1[4];
            #pragma unroll
            for (int nf = 0; nf < 8; ++nf) {
                uint32_t bf[2];
                const uint32_t* kr = &sm.ks[(nf * 8 + g) * QSTR + ks * 8 + t];
                bf[0] = kr[0]; bf[1] = kr[4];
                mma8(s[nf], a, bf);
            }
        }

        #pragma unroll
        for (int nf = 0; nf < 8; ++nf)
            #pragma unroll
            for (int j = 0; j < 4; ++j) s[nf][j] *= SCALE_F;

        if (kt >= 2 * qt) {  // causal mask on diagonal tiles
            int r0 = qt * 128 + qb + g, r1 = r0 + 8;
            #pragma unroll
            for (int nf = 0; nf < 8; ++nf) {
                int c0 = kt * 64 + nf * 8 + 2 * t, c1 = c0 + 1;
                if (c0 > r0) s[nf][0] = -1e30f;
                if (c1 > r0) s[nf][1] = -1e30f;
                if (c0 > r1) s[nf][2] = -1e30f;
                if (c1 > r1) s[nf][3] = -1e30f;
            }
        }

        // ---- online softmax (rows g and g+8 of this warp) ----
        float mx0 = -FLT_MAX, mx1 = -FLT_MAX;
        #pragma unroll
        for (int nf = 0; nf < 8; ++nf) {
            mx0 = fmaxf(mx0, fmaxf(s[nf][0], s[nf][1]));
            mx1 = fmaxf(mx1, fmaxf(s[nf][2], s[nf][3]));
        }
        mx0 = fmaxf(mx0, __shfl_xor_sync(0xffffffffu, mx0, 1));
        mx0 = fmaxf(mx0, __shfl_xor_sync(0xffffffffu, mx0, 2));
        mx1 = fmaxf(mx1, __shfl_xor_sync(0xffffffffu, mx1, 1));
        mx1 = fmaxf(mx1, __shfl_xor_sync(0xffffffffu, mx1, 2));
        float mn0 = fmaxf(m0, mx0), mn1 = fmaxf(m1, mx1);
        float cf0 = __expf(m0 - mn0), cf1 = __expf(m1 - mn1);
        float sum0 = 0.f, sum1 = 0.f;
        #pragma unroll
        for (int nf = 0; nf < 8; ++nf) {
            float p00 = __expf(s[nf][0] - mn0);
            float p01 = __expf(s[nf][1] - mn0);
            float p10 = __expf(s[nf][2] - mn1);
            float p11 = __expf(s[nf][3] - mn1);
            sum0 += p00 + p01; sum1 += p10 + p11;
            *(uint2*)&sm.ps[(qb + g) * PSTR + nf * 8 + 2 * t]     = make_uint2(f2tf(p00), f2tf(p01));
            *(uint2*)&sm.ps[(qb + g + 8) * PSTR + nf * 8 + 2 * t] = make_uint2(f2tf(p10), f2tf(p11));
        }
        sum0 += __shfl_xor_sync(0xffffffffu, sum0, 1);
        sum0 += __shfl_xor_sync(0xffffffffu, sum0, 2);
        sum1 += __shfl_xor_sync(0xffffffffu, sum1, 1);
        sum1 += __shfl_xor_sync(0xffffffffu, sum1, 2);
        l0 = l0 * cf0 + sum0; l1 = l1 * cf1 + sum1;
        m0 = mn0; m1 = mn1;
        #pragma unroll
        for (int nf = 0; nf < 16; ++nf) {
            oacc[nf][0] *= cf0; oacc[nf][1] *= cf0;
            oacc[nf][2] *= cf1; oacc[nf][3] *= cf1;
        }
        __syncwarp();   // P stores visible to quad-mates before A-frag loads

        // ---- O += P V ---- (ps rows of this warp only -> no block sync needed)
        #pragma unroll
        for (int ks2 = 0; ks2 < 8; ++ks2) {
            uint32_t a[4];
            const uint32_t* p0 = &sm.ps[(qb + g) * PSTR + ks2 * 8 + t];
            const uint32_t* p1 = &sm.ps[(qb + g + 8) * PSTR + ks2 * 8 + t];
            a[0] = p0[0]; a[1] = p1[0]; a[2] = p0[4]; a[3] = p1[4];
            #pragma unroll
            for (int nf = 0; nf < 16; ++nf) {
                uint32_t bf[2];
                bf[0] = sm.vs[(ks2 * 8 + t) * VSTR + nf * 8 + g];
                bf[1] = sm.vs[(ks2 * 8 + t + 4) * VSTR + nf * 8 + g];
                mma8(oacc[nf], a, bf);
            }
        }
    }

    // ---- epilogue ----
    float inv0 = 1.f / l0, inv1 = 1.f / l1;
    int r0 = qt * 128 + qb + g;
    float* o0 = o + ((size_t)(b * LSEQ + r0) * NHEADS + h) * HDIM;
    float* o1 = o0 + (size_t)8 * NHEADS * HDIM;
    #pragma unroll
    for (int nf = 0; nf < 16; ++nf) {
        *(float2*)&o0[nf * 8 + 2 * t] = make_float2(oacc[nf][0] * inv0, oacc[nf][1] * inv0);
        *(float2*)&o1[nf * 8 + 2 * t] = make_float2(oacc[nf][2] * inv1, oacc[nf][3] * inv1);
    }
    if (qt == 7 && t == 0) {
        g_ml[(b * NHEADS + h) * SAMPLE_Q + qb + g]     = make_float2(m0, l0);
        g_ml[(b * NHEADS + h) * SAMPLE_Q + qb + g + 8] = make_float2(m1, l1);
    }
}

// ---------------- SnapKV sample scores (tf32 mma) ----------------
struct SampSmem {
    uint32_t qs[128 * QSTR];
    uint32_t ks[64 * QSTR];
    float colpart[8][64];
};

__global__ void __launch_bounds__(256)
sample_kernel(const float* __restrict__ q, const float* __restrict__ k)
{
    extern __shared__ char raw[];
    SampSmem& sm = *reinterpret_cast<SampSmem*>(raw);

    const int kt = blockIdx.x;          // 16 k-tiles of 64
    const int bh = blockIdx.y;          // 128
    const int b = bh >> 5, h = bh & 31, kvh = h >> 2;
    const int tid = threadIdx.x;
    const int w = tid >> 5, lane = tid & 31;
    const int g = lane >> 2, t = lane & 3;
    const int qb = w * 16;

    {
        const float* qg = q + ((size_t)(b * LSEQ + (LSEQ - SAMPLE_Q) + qb) * NHEADS + h) * HDIM;
        #pragma unroll 4
        for (int r = 0; r < 16; ++r) {
            float4 f = *(const float4*)(qg + (size_t)r * NHEADS * HDIM + lane * 4);
            uint32_t* d = &sm.qs[(qb + r) * QSTR + lane * 4];
            d[0] = f2tf(f.x); d[1] = f2tf(f.y); d[2] = f2tf(f.z); d[3] = f2tf(f.w);
        }
        const float* kg = k + ((size_t)(b * LSEQ + kt * 64 + w * 8) * NKV + kvh) * HDIM;
        #pragma unroll
        for (int r = 0; r < 8; ++r) {
            float4 f = *(const float4*)(kg + (size_t)r * NKV * HDIM + lane * 4);
            uint32_t* d = &sm.ks[(w * 8 + r) * QSTR + lane * 4];
            d[0] = f2tf(f.x); d[1] = f2tf(f.y); d[2] = f2tf(f.z); d[3] = f2tf(f.w);
        }
    }
    __syncthreads();

    float s[8][4];
    #pragma unroll
    for (int nf = 0; nf < 8; ++nf)
        #pragma unroll
        for (int j = 0; j < 4; ++j) s[nf][j] = 0.f;

    #pragma unroll
    for (int ks = 0; ks < 16; ++ks) {
        uint32_t a[4];
        const uint32_t* q0 = &sm.qs[(qb + g) * QSTR + ks * 8 + t];
        const uint32_t* q1 = &sm.qs[(qb + g + 8) * QSTR + ks * 8 + t];
        a[0] = q0[0]; a[1] = q1[0]; a[2] = q0[4]; a[3] = q1[4];
        #pragma unroll
        for (int nf = 0; nf < 8; ++nf) {
            uint32_t bf[2];
            const uint32_t* kr = &sm.ks[(nf * 8 + g) * QSTR + ks * 8 + t];
            bf[0] = kr[0]; bf[1] = kr[4];
            mma8(s[nf], a, bf);
        }
    }

    float2 ml0 = g_ml[bh * SAMPLE_Q + qb + g];
    float2 ml1 = g_ml[bh * SAMPLE_Q + qb + g + 8];
    float il0 = 1.f / ml0.y, il1 = 1.f / ml1.y;
    int r0 = (LSEQ - SAMPLE_Q) + qb + g, r1 = r0 + 8;

    float cp[16];
    #pragma unroll
    for (int j = 0; j < 16; ++j) cp[j] = 0.f;
    #pragma unroll
    for (int nf = 0; nf < 8; ++nf) {
        int c0 = kt * 64 + nf * 8 + 2 * t, c1 = c0 + 1;
        float p00 = (c0 <= r0) ? __expf(s[nf][0] * SCALE_F - ml0.x) * il0 : 0.f;
        float p01 = (c1 <= r0) ? __expf(s[nf][1] * SCALE_F - ml0.x) * il0 : 0.f;
        float p10 = (c0 <= r1) ? __expf(s[nf][2] * SCALE_F - ml1.x) * il1 : 0.f;
        float p11 = (c1 <= r1) ? __expf(s[nf][3] * SCALE_F - ml1.x) * il1 : 0.f;
        cp[nf * 2]     += p00 + p10;
        cp[nf * 2 + 1] += p01 + p11;
    }
    // reduce over g (lanes l = 4g+t share t)
    #pragma unroll
    for (int d = 4; d < 32; d <<= 1)
        #pragma unroll
        for (int j = 0; j < 16; ++j)
            cp[j] += __shfl_xor_sync(0xffffffffu, cp[j], d);
    if (g == 0) {
        #pragma unroll
        for (int nf = 0; nf < 8; ++nf) {
            sm.colpart[w][nf * 8 + 2 * t]     = cp[nf * 2];
            sm.colpart[w][nf * 8 + 2 * t + 1] = cp[nf * 2 + 1];
        }
    }
    __syncthreads();
    if (tid < 64) {
        float ssum = 0.f;
        #pragma unroll
        for (int ww = 0; ww < 8; ++ww) ssum += sm.colpart[ww][tid];
        g_part[(size_t)bh * LSEQ + kt * 64 + tid] = ssum;
    }
}

// ---------------- deterministic reduce over heads ----------------
__global__ void reduce_kernel() {
    int idx = blockIdx.x * 256 + threadIdx.x;   // 4096
    int b = idx >> 10, kk = idx & 1023;
    float s = 0.f;
    #pragma unroll
    for (int h = 0; h < NHEADS; ++h)
        s += g_part[(size_t)(b * NHEADS + h) * LSEQ + kk];
    g_imp[idx] = s;
}

// ---------------- exact top-512 + ascending sort ----------------
__global__ void topk_kernel() {
    const int b = blockIdx.x;
    const int tid = threadIdx.x;                // 1024
    __shared__ float vals[LSEQ];
    __shared__ unsigned flags[32];
    vals[tid] = g_imp[b * LSEQ + tid];
    __syncthreads();
    float v = vals[tid];
    int cnt = 0;
    for (int j = 0; j < LSEQ; ++j) {
        float wv = vals[j];
        cnt += (wv > v) || (wv == v && j < tid);
    }
    bool kept = (cnt < KEEP);
    unsigned bal = __ballot_sync(0xffffffffu, kept);
    if ((tid & 31) == 0) flags[tid >> 5] = bal;
    __syncthreads();
    if (kept) {
        int wq = tid >> 5;
        int pos = 0;
        for (int tq = 0; tq < wq; ++tq) pos += __popc(flags[tq]);
        pos += __popc(flags[wq] & ((1u << (tid & 31)) - 1u));
        g_keep[b * KEEP + pos] = tid;
    }
}

// ---------------- gather kept tokens, scatter to cache slots ----------------
__global__ void scatter_kernel(const float* __restrict__ k, const float* __restrict__ v,
                               const int* __restrict__ slot_map,
                               float* __restrict__ kco, float* __restrict__ vco) {
    int r = blockIdx.x;                         // 2048 rows
    int b = r >> 9, j = r & 511;
    int src = b * LSEQ + g_keep[b * KEEP + j];
    int dst = slot_map[b * LSEQ + j];
    const float4* ks = (const float4*)(k + (size_t)src * (NKV * HDIM));
    const float4* vs = (const float4*)(v + (size_t)src * (NKV * HDIM));
    float4* kd = (float4*)(kco + (size_t)dst * (NKV * HDIM));
    float4* vd = (float4*)(vco + (size_t)dst * (NKV * HDIM));
    kd[threadIdx.x] = ks[threadIdx.x];
    vd[threadIdx.x] = vs[threadIdx.x];
}

// ---------------- launch ----------------
extern "C" void kernel_launch(void* const* d_in, const int* in_sizes, int n_in,
                              void* d_out, int out_size) {
    const float* q  = (const float*)d_in[0];
    const float* k  = (const float*)d_in[1];
    const float* v  = (const float*)d_in[2];
    const float* kc = (const float*)d_in[3];
    const float* vc = (const float*)d_in[4];
    const int* slot = (const int*)d_in[5];

    float* o   = (float*)d_out;
    float* kco = o + (size_t)BATCH * LSEQ * NHEADS * HDIM;
    float* vco = kco + (size_t)8192 * (NKV * HDIM);

    cudaFuncSetAttribute(attn_kernel, cudaFuncAttributeMaxDynamicSharedMemorySize, (int)sizeof(AttnSmem));
    cudaFuncSetAttribute(sample_kernel, cudaFuncAttributeMaxDynamicSharedMemorySize, (int)sizeof(SampSmem));

    copy_caches_kernel<<<8192, 256>>>((const float4*)kc, (const float4*)vc,
                                      (float4*)kco, (float4*)vco);
    attn_kernel<<<dim3(8, NHEADS, BATCH), 256, sizeof(AttnSmem)>>>(q, k, v, o);
    sample_kernel<<<dim3(16, BATCH * NHEADS), 256, sizeof(SampSmem)>>>(q, k);
    reduce_kernel<<<16, 256>>>();
    topk_kernel<<<BATCH, 1024>>>();
    scatter_kernel<<<2048, 256>>>(k, v, slot, kco, vco);
}